// round 2
// baseline (speedup 1.0000x reference)
#include <cuda_runtime.h>
#include <cstdint>

#define BATCH   8
#define VN      201
#define DIM     256
#define PAIRS   20301          /* VN*(VN+1)/2 */
#define MROWS   162408         /* BATCH*PAIRS  */
#define TILESM  1269           /* ceil(MROWS/128) */
#define KSEL    100
#define LSLOPE  0.01f
#define CNT     323208.0       /* BATCH*VN*VN */

// ---------------- device scratch (no cudaMalloc allowed) ----------------
__device__ float g_bufA[MROWS * 256];
__device__ float g_bufB[MROWS * 256];
__device__ int2  g_vw[PAIRS];
__device__ float g_wpair[PAIRS];
__device__ float g_psum[TILESM * 256];
__device__ float g_psq [TILESM * 256];
__device__ float g_sArr[1024];
__device__ float g_tArr[1024];
__device__ float g_logits[BATCH * VN * VN];

// ---------------- f32x2 packed-FMA helpers ----------------
__device__ __forceinline__ unsigned long long pk2(float a) {
    unsigned long long r; unsigned int u = __float_as_uint(a);
    asm("mov.b64 %0, {%1, %1};" : "=l"(r) : "r"(u));
    return r;
}
__device__ __forceinline__ void fma2(unsigned long long& d, unsigned long long a, unsigned long long b) {
    asm("fma.rn.f32x2 %0, %1, %2, %0;" : "+l"(d) : "l"(a), "l"(b));
}
__device__ __forceinline__ void unpk2(unsigned long long v, float& lo, float& hi) {
    unsigned int l, h;
    asm("mov.b64 {%0, %1}, %2;" : "=r"(l), "=r"(h) : "l"(v));
    lo = __uint_as_float(l); hi = __uint_as_float(h);
}

// ---------------- init: pair -> (v,w) LUT + BN weights ----------------
__global__ void init_lut() {
    int t = threadIdx.x;
    for (int v = t; v < VN; v += blockDim.x) {
        int base = v * VN - (v * (v - 1)) / 2;
        for (int w = v; w < VN; w++) {
            int p = base + (w - v);
            g_vw[p] = make_int2(v, w);
            g_wpair[p] = (v == w) ? 1.0f : 2.0f;
        }
    }
}

// ---------------- pairwise |x_v - x_w| into packed half-matrix ----------------
__global__ void absdiff_kernel(const float* __restrict__ x) {
    int idx = blockIdx.x * blockDim.x + threadIdx.x;
    if (idx >= MROWS * 64) return;
    int r  = idx >> 6;
    int cq = idx & 63;
    int b = r / PAIRS, p = r - b * PAIRS;
    int2 vw = g_vw[p];
    const float4 xv = *(const float4*)&x[(size_t)(b * VN + vw.x) * 256 + cq * 4];
    const float4 xw = *(const float4*)&x[(size_t)(b * VN + vw.y) * 256 + cq * 4];
    float4 o;
    o.x = fabsf(xv.x - xw.x); o.y = fabsf(xv.y - xw.y);
    o.z = fabsf(xv.z - xw.z); o.w = fabsf(xv.w - xw.w);
    *(float4*)&g_bufA[(size_t)r * 256 + cq * 4] = o;
}

// ---------------- fused GEMM: C = act(affine(A)) @ W^T + bias, + BN partial stats ----------------
// A row-major [MROWS, K], W row-major [Ntot, K], C row-major [MROWS, ldc].
template<bool AFFINE, bool SWAP>
__global__ __launch_bounds__(256, 2)
void gemm_bn(int K, int ldc, int affOff,
             const float* __restrict__ W, const float* __restrict__ bias)
{
    const float* A  = SWAP ? g_bufB : g_bufA;
    float*       C  = SWAP ? g_bufA : g_bufB;

    __shared__ float As[16][132];
    __shared__ float Bs[16][132];

    const int t = threadIdx.x;
    const int tm = blockIdx.x, tn = blockIdx.y;
    const int rowBase = tm * 128, colBase = tn * 128;
    const int ar = t >> 2;                 // 0..63
    const int ac = (t & 3) << 2;           // 0,4,8,12

    unsigned long long acc[8][4];
#pragma unroll
    for (int i = 0; i < 8; i++)
#pragma unroll
        for (int j = 0; j < 4; j++) acc[i][j] = 0ull;

    const bool v0 = (rowBase + ar)      < MROWS;
    const bool v1 = (rowBase + ar + 64) < MROWS;
    const float* Ag0 = A + (size_t)(rowBase + ar) * K + ac;
    const float* Ag1 = A + (size_t)(rowBase + ar + 64) * K + ac;
    const float* Wg0 = W + (size_t)(colBase + ar) * K + ac;
    const float* Wg1 = W + (size_t)(colBase + ar + 64) * K + ac;

    const int ty = t >> 4, tx = t & 15;

    for (int kc = 0; kc < K; kc += 16) {
        float4 a0 = make_float4(0.f, 0.f, 0.f, 0.f), a1 = a0;
        if (v0) a0 = *(const float4*)(Ag0 + kc);
        if (v1) a1 = *(const float4*)(Ag1 + kc);
        float4 b0 = *(const float4*)(Wg0 + kc);
        float4 b1 = *(const float4*)(Wg1 + kc);

        if (AFFINE) {
            float4 s4 = *(const float4*)&g_sArr[affOff + kc + ac];
            float4 t4 = *(const float4*)&g_tArr[affOff + kc + ac];
            a0.x = a0.x * s4.x + t4.x; a0.x = a0.x >= 0.f ? a0.x : LSLOPE * a0.x;
            a0.y = a0.y * s4.y + t4.y; a0.y = a0.y >= 0.f ? a0.y : LSLOPE * a0.y;
            a0.z = a0.z * s4.z + t4.z; a0.z = a0.z >= 0.f ? a0.z : LSLOPE * a0.z;
            a0.w = a0.w * s4.w + t4.w; a0.w = a0.w >= 0.f ? a0.w : LSLOPE * a0.w;
            a1.x = a1.x * s4.x + t4.x; a1.x = a1.x >= 0.f ? a1.x : LSLOPE * a1.x;
            a1.y = a1.y * s4.y + t4.y; a1.y = a1.y >= 0.f ? a1.y : LSLOPE * a1.y;
            a1.z = a1.z * s4.z + t4.z; a1.z = a1.z >= 0.f ? a1.z : LSLOPE * a1.z;
            a1.w = a1.w * s4.w + t4.w; a1.w = a1.w >= 0.f ? a1.w : LSLOPE * a1.w;
        }

        As[ac + 0][ar] = a0.x; As[ac + 1][ar] = a0.y; As[ac + 2][ar] = a0.z; As[ac + 3][ar] = a0.w;
        As[ac + 0][ar + 64] = a1.x; As[ac + 1][ar + 64] = a1.y; As[ac + 2][ar + 64] = a1.z; As[ac + 3][ar + 64] = a1.w;
        Bs[ac + 0][ar] = b0.x; Bs[ac + 1][ar] = b0.y; Bs[ac + 2][ar] = b0.z; Bs[ac + 3][ar] = b0.w;
        Bs[ac + 0][ar + 64] = b1.x; Bs[ac + 1][ar + 64] = b1.y; Bs[ac + 2][ar + 64] = b1.z; Bs[ac + 3][ar + 64] = b1.w;
        __syncthreads();

#pragma unroll
        for (int k = 0; k < 16; k++) {
            float4 av0 = *(const float4*)&As[k][ty * 8];
            float4 av1 = *(const float4*)&As[k][ty * 8 + 4];
            ulonglong2 bv0 = *(const ulonglong2*)&Bs[k][tx * 8];
            ulonglong2 bv1 = *(const ulonglong2*)&Bs[k][tx * 8 + 4];
            unsigned long long bb[4] = { bv0.x, bv0.y, bv1.x, bv1.y };
            float aa[8] = { av0.x, av0.y, av0.z, av0.w, av1.x, av1.y, av1.z, av1.w };
#pragma unroll
            for (int i = 0; i < 8; i++) {
                unsigned long long ap = pk2(aa[i]);
#pragma unroll
                for (int j = 0; j < 4; j++) fma2(acc[i][j], ap, bb[j]);
            }
        }
        __syncthreads();
    }

    // ---------- epilogue: bias add, store, weighted per-channel partial sums ----------
    float4 bb0 = *(const float4*)&bias[colBase + tx * 8];
    float4 bb1 = *(const float4*)&bias[colBase + tx * 8 + 4];
    float psumL[8] = {0,0,0,0,0,0,0,0};
    float psqL [8] = {0,0,0,0,0,0,0,0};

#pragma unroll
    for (int i = 0; i < 8; i++) {
        int gr = rowBase + ty * 8 + i;
        bool ok = gr < MROWS;
        float wt = ok ? g_wpair[gr % PAIRS] : 0.f;
        float y[8];
#pragma unroll
        for (int j = 0; j < 4; j++) unpk2(acc[i][j], y[2 * j], y[2 * j + 1]);
        y[0] += bb0.x; y[1] += bb0.y; y[2] += bb0.z; y[3] += bb0.w;
        y[4] += bb1.x; y[5] += bb1.y; y[6] += bb1.z; y[7] += bb1.w;
        if (ok) {
            float4 o0 = make_float4(y[0], y[1], y[2], y[3]);
            float4 o1 = make_float4(y[4], y[5], y[6], y[7]);
            *(float4*)&C[(size_t)gr * ldc + colBase + tx * 8]     = o0;
            *(float4*)&C[(size_t)gr * ldc + colBase + tx * 8 + 4] = o1;
        }
#pragma unroll
        for (int j = 0; j < 8; j++) { psumL[j] += wt * y[j]; psqL[j] += wt * y[j] * y[j]; }
    }

    // deterministic reduction over the 16 ty groups via smem
    float* sred = &As[0][0];   // 2112 floats >= 2048
    __syncthreads();
#pragma unroll
    for (int j = 0; j < 8; j++) sred[ty * 128 + tx * 8 + j] = psumL[j];
    __syncthreads();
    if (t < 128) {
        float s = 0.f;
#pragma unroll
        for (int i = 0; i < 16; i++) s += sred[i * 128 + t];
        g_psum[(size_t)tm * ldc + colBase + t] = s;
    }
    __syncthreads();
#pragma unroll
    for (int j = 0; j < 8; j++) sred[ty * 128 + tx * 8 + j] = psqL[j];
    __syncthreads();
    if (t < 128) {
        float s = 0.f;
#pragma unroll
        for (int i = 0; i < 16; i++) s += sred[i * 128 + t];
        g_psq[(size_t)tm * ldc + colBase + t] = s;
    }
}

// ---------------- reduce partials -> BN affine (s,t) per channel ----------------
__global__ void stats_kernel(int outOff, int Ntot,
                             const float* __restrict__ gamma, const float* __restrict__ beta)
{
    int c = blockIdx.x;
    int t = threadIdx.x;
    double s = 0.0, q = 0.0;
    for (int i = t; i < TILESM; i += 256) {
        s += (double)g_psum[(size_t)i * Ntot + c];
        q += (double)g_psq [(size_t)i * Ntot + c];
    }
    __shared__ double rs[256], rq[256];
    rs[t] = s; rq[t] = q;
    __syncthreads();
    for (int st = 128; st > 0; st >>= 1) {
        if (t < st) { rs[t] += rs[t + st]; rq[t] += rq[t + st]; }
        __syncthreads();
    }
    if (t == 0) {
        double mean = rs[0] / CNT;
        double var  = rq[0] / CNT - mean * mean;
        float inv = rsqrtf((float)var + 1e-5f);
        float sc  = gamma[c] * inv;
        g_sArr[outOff + c] = sc;
        g_tArr[outOff + c] = beta[c] - (float)mean * sc;
    }
}

// ---------------- final linear -> symmetric logit scatter ----------------
__global__ void logits_kernel(const float* __restrict__ w4, const float* __restrict__ b4)
{
    int warp = threadIdx.x >> 5, lane = threadIdx.x & 31;
    int r = blockIdx.x * 8 + warp;
    if (r >= MROWS) return;
    int c = lane * 4;
    float4 v  = *(const float4*)&g_bufA[(size_t)r * 128 + c];
    float4 s4 = *(const float4*)&g_sArr[768 + c];
    float4 t4 = *(const float4*)&g_tArr[768 + c];
    float4 w  = *(const float4*)&w4[c];
    float a, sum = 0.f;
    a = v.x * s4.x + t4.x; a = a >= 0.f ? a : LSLOPE * a; sum += a * w.x;
    a = v.y * s4.y + t4.y; a = a >= 0.f ? a : LSLOPE * a; sum += a * w.y;
    a = v.z * s4.z + t4.z; a = a >= 0.f ? a : LSLOPE * a; sum += a * w.z;
    a = v.w * s4.w + t4.w; a = a >= 0.f ? a : LSLOPE * a; sum += a * w.w;
#pragma unroll
    for (int off = 16; off > 0; off >>= 1) sum += __shfl_down_sync(0xffffffffu, sum, off);
    if (lane == 0) {
        float lg = sum + b4[0];
        int b = r / PAIRS, p = r - b * PAIRS;
        int2 vw = g_vw[p];
        g_logits[((size_t)b * VN + vw.x) * VN + vw.y] = lg;
        g_logits[((size_t)b * VN + vw.y) * VN + vw.x] = lg;
    }
}

// ---------------- row softmax + top-K mask ----------------
__global__ void softmax_topk(float* __restrict__ out)
{
    int bv = blockIdx.x;
    int b = bv / VN, v = bv % VN;
    int t = threadIdx.x;
    __shared__ float sl[204];
    __shared__ float red[256];

    float lv = -3.402823466e38f;
    if (t < VN) { lv = g_logits[((size_t)b * VN + v) * VN + t]; sl[t] = lv; }
    red[t] = lv;
    __syncthreads();
    for (int s = 128; s > 0; s >>= 1) {
        if (t < s) red[t] = fmaxf(red[t], red[t + s]);
        __syncthreads();
    }
    float mx = red[0];
    __syncthreads();
    float e = (t < VN) ? __expf(lv - mx) : 0.f;
    red[t] = e;
    __syncthreads();
    for (int s = 128; s > 0; s >>= 1) {
        if (t < s) red[t] += red[t + s];
        __syncthreads();
    }
    float inv = 1.f / red[0];
    if (t < VN) {
        int cnt = 0;
        for (int j = 0; j < VN; j++) {
            float lj = sl[j];
            cnt += (lj > lv) || (lj == lv && j < t);
        }
        out[((size_t)b * VN + v) * VN + t] = (cnt < KSEL) ? e * inv : 0.f;
    }
}

// ---------------- launch ----------------
extern "C" void kernel_launch(void* const* d_in, const int* in_sizes, int n_in,
                              void* d_out, int out_size)
{
    (void)in_sizes; (void)n_in; (void)out_size;
    const float* x   = (const float*)d_in[0];
    const float* w0  = (const float*)d_in[1];
    const float* b0  = (const float*)d_in[2];
    const float* g0  = (const float*)d_in[3];
    const float* be0 = (const float*)d_in[4];
    const float* w1  = (const float*)d_in[5];
    const float* b1  = (const float*)d_in[6];
    const float* g1  = (const float*)d_in[7];
    const float* be1 = (const float*)d_in[8];
    const float* w2  = (const float*)d_in[9];
    const float* b2  = (const float*)d_in[10];
    const float* g2  = (const float*)d_in[11];
    const float* be2 = (const float*)d_in[12];
    const float* w3  = (const float*)d_in[13];
    const float* b3  = (const float*)d_in[14];
    const float* g3  = (const float*)d_in[15];
    const float* be3 = (const float*)d_in[16];
    const float* w4  = (const float*)d_in[17];
    const float* b4  = (const float*)d_in[18];

    init_lut<<<1, 256>>>();
    absdiff_kernel<<<(MROWS * 64 + 255) / 256, 256>>>(x);

    // L0: bufA(absdiff, K=256) -> bufB (N=256)
    gemm_bn<false, false><<<dim3(TILESM, 2), 256>>>(256, 256, 0, w0, b0);
    stats_kernel<<<256, 256>>>(0, 256, g0, be0);

    // L1: bufB -> bufA (K=256, N=256), affine of layer0 stats
    gemm_bn<true, true><<<dim3(TILESM, 2), 256>>>(256, 256, 0, w1, b1);
    stats_kernel<<<256, 256>>>(256, 256, g1, be1);

    // L2: bufA -> bufB (K=256, N=128)
    gemm_bn<true, false><<<dim3(TILESM, 1), 256>>>(256, 128, 256, w2, b2);
    stats_kernel<<<128, 256>>>(512, 128, g2, be2);

    // L3: bufB -> bufA (K=128, N=128)
    gemm_bn<true, true><<<dim3(TILESM, 1), 256>>>(128, 128, 512, w3, b3);
    stats_kernel<<<128, 256>>>(768, 128, g3, be3);

    // L4: bufA -> symmetric logits
    logits_kernel<<<MROWS / 8, 256>>>(w4, b4);

    // softmax over axis-2 + top-K mask
    softmax_topk<<<BATCH * VN, 256>>>((float*)d_out);
}

// round 4
// speedup vs baseline: 1.7019x; 1.7019x over previous
#include <cuda_runtime.h>
#include <cuda_bf16.h>
#include <cstdint>

#define BATCH   8
#define VN      201
#define PAIRS   20301
#define MROWS   162408
#define TILESM  1269
#define KSEL    100
#define LSLOPE  0.01f
#define CNT     323208.0
#define NCTA    148
#define PSTRIDE 160

// ---------------- device scratch ----------------
__device__ float g_bufA[MROWS * 256];
__device__ float g_bufB[MROWS * 256];
__device__ int2  g_vw[PAIRS];
__device__ float g_wpair[PAIRS];
__device__ float g_psum[256 * PSTRIDE];
__device__ float g_psq [256 * PSTRIDE];
__device__ float g_sArr[1024];
__device__ float g_tArr[1024];
__device__ float g_logits[BATCH * VN * VN];
__device__ __nv_bfloat16 g_whi[180224];
__device__ __nv_bfloat16 g_wlo[180224];

// ---------------- PTX helpers ----------------
__device__ __forceinline__ uint32_t smem_u32(const void* p) {
    uint32_t a;
    asm("{ .reg .u64 t; cvta.to.shared.u64 t, %1; cvt.u32.u64 %0, t; }" : "=r"(a) : "l"(p));
    return a;
}
#define STS128(r0, r1, r2, r3, a) \
    asm volatile("st.shared.v4.b32 [%0], {%1, %2, %3, %4};" \
                 :: "r"(a), "r"(r0), "r"(r1), "r"(r2), "r"(r3) : "memory")
#define LDSM4(R, a) \
    asm volatile("ldmatrix.sync.aligned.m8n8.x4.shared.b16 {%0,%1,%2,%3}, [%4];" \
                 : "=r"((R)[0]), "=r"((R)[1]), "=r"((R)[2]), "=r"((R)[3]) : "r"(a))
#define MMA16816(c, A, b0, b1) \
    asm volatile("mma.sync.aligned.m16n8k16.row.col.f32.bf16.bf16.f32 " \
                 "{%0,%1,%2,%3}, {%4,%5,%6,%7}, {%8,%9}, {%0,%1,%2,%3};" \
                 : "+f"((c)[0]), "+f"((c)[1]), "+f"((c)[2]), "+f"((c)[3]) \
                 : "r"((A)[0]), "r"((A)[1]), "r"((A)[2]), "r"((A)[3]), "r"(b0), "r"(b1))

// ---------------- init: pair LUT ----------------
__global__ void init_lut() {
    int t = threadIdx.x;
    for (int v = t; v < VN; v += blockDim.x) {
        int base = v * VN - (v * (v - 1)) / 2;
        for (int w = v; w < VN; w++) {
            int p = base + (w - v);
            g_vw[p] = make_int2(v, w);
            g_wpair[p] = (v == w) ? 1.0f : 2.0f;
        }
    }
}

// ---------------- weight split fp32 -> bf16 hi/lo ----------------
__global__ void wsplit(const float* __restrict__ w0, const float* __restrict__ w1,
                       const float* __restrict__ w2, const float* __restrict__ w3) {
    int t = blockIdx.x * blockDim.x + threadIdx.x;
    int st = gridDim.x * blockDim.x;
    for (int i = t; i < 65536; i += st) {
        float v = w0[i]; __nv_bfloat16 h = __float2bfloat16(v);
        g_whi[i] = h; g_wlo[i] = __float2bfloat16(v - __bfloat162float(h));
    }
    for (int i = t; i < 65536; i += st) {
        float v = w1[i]; __nv_bfloat16 h = __float2bfloat16(v);
        g_whi[65536 + i] = h; g_wlo[65536 + i] = __float2bfloat16(v - __bfloat162float(h));
    }
    for (int i = t; i < 32768; i += st) {
        float v = w2[i]; __nv_bfloat16 h = __float2bfloat16(v);
        g_whi[131072 + i] = h; g_wlo[131072 + i] = __float2bfloat16(v - __bfloat162float(h));
    }
    for (int i = t; i < 16384; i += st) {
        float v = w3[i]; __nv_bfloat16 h = __float2bfloat16(v);
        g_whi[163840 + i] = h; g_wlo[163840 + i] = __float2bfloat16(v - __bfloat162float(h));
    }
}

// ---------------- persistent mma.sync bf16-split GEMM, fused producer + BN partials ----------------
// MODE 0: A = |x_v - x_w| on the fly.  MODE 1: A = LeakyReLU(affine(prev)).
// SRC 0: Ain=g_bufA, C=g_bufB.  SRC 1: Ain=g_bufB, C=g_bufA.
template<int K, int MODE, int SRC>
__global__ __launch_bounds__(256, 1)
void gemm_mma(int ldc, int wOff, const float* __restrict__ x,
              const float* __restrict__ bias, int affOff)
{
    constexpr int NC   = K / 64;
    constexpr int OFFA = 8192;
    constexpr int OFFB = OFFA + 32768;
    const float* Ain  = (SRC == 0) ? g_bufA : g_bufB;
    float*       Cout = (SRC == 0) ? g_bufB : g_bufA;

    extern __shared__ char sm[];
    uint32_t sb = smem_u32(sm);
    const int tid  = threadIdx.x;
    const int lane = tid & 31;
    const int w    = tid >> 5;
    const int wm   = w & 1, wn = w >> 1;
    const int colStart = blockIdx.y * 128;

    float* biasS  = (float*)(sm + 0);
    float* sumAcc = (float*)(sm + 512);
    float* sqAcc  = (float*)(sm + 1024);
    float* sS     = (float*)(sm + 1536);
    float* tS     = (float*)(sm + 2560);
    float* wSsum  = (float*)(sm + 3584);
    float* wSsq   = (float*)(sm + 4608);

    if (tid < 128) { biasS[tid] = bias[colStart + tid]; sumAcc[tid] = 0.f; sqAcc[tid] = 0.f; }
    if (MODE == 1) {
        for (int i = tid; i < K; i += 256) { sS[i] = g_sArr[affOff + i]; tS[i] = g_tArr[affOff + i]; }
    }

    // ---- B (weight hi/lo) resident in smem, SW128 swizzled [n][64k] rows ----
    for (int i = tid; i < NC * 128; i += 256) {
        int c = i >> 7, n = i & 127;
        const uint4* srcH = (const uint4*)(g_whi + (size_t)wOff + (size_t)(colStart + n) * K + c * 64);
        const uint4* srcL = (const uint4*)(g_wlo + (size_t)wOff + (size_t)(colStart + n) * K + c * 64);
        uint32_t baseH = sb + OFFB + c * 16384;
        uint32_t baseL = sb + OFFB + NC * 16384 + c * 16384;
#pragma unroll
        for (int u = 0; u < 8; u++) {
            uint4 vH = srcH[u]; uint4 vL = srcL[u];
            uint32_t o = n * 128 + u * 16; o ^= (o >> 3) & 0x70;
            STS128(vH.x, vH.y, vH.z, vH.w, baseH + o);
            STS128(vL.x, vL.y, vL.z, vL.w, baseL + o);
        }
    }

    const int prow = tid >> 1, phalf = tid & 1;

    for (int mt = blockIdx.x; mt < TILESM; mt += NCTA) {
        int gr = mt * 128 + prow;
        bool ok = gr < MROWS;
        int vv = 0, ww = 0, bb = 0;
        if (MODE == 0 && ok) {
            bb = gr / PAIRS; int p = gr - bb * PAIRS;
            int2 vw2 = g_vw[p]; vv = vw2.x; ww = vw2.y;
        }

        float facc[4][4][4];
#pragma unroll
        for (int i = 0; i < 4; i++)
#pragma unroll
            for (int j = 0; j < 4; j++)
#pragma unroll
                for (int q = 0; q < 4; q++) facc[i][j][q] = 0.f;

        float fa[32];
        // load chunk 0
        {
            int kb = phalf * 32;
            if (ok) {
                if (MODE == 0) {
                    const float4* pv = (const float4*)(x + ((size_t)(bb * VN + vv)) * 256 + kb);
                    const float4* pw = (const float4*)(x + ((size_t)(bb * VN + ww)) * 256 + kb);
#pragma unroll
                    for (int i = 0; i < 8; i++) {
                        float4 fv = pv[i], fw = pw[i];
                        fa[4*i+0] = fabsf(fv.x - fw.x); fa[4*i+1] = fabsf(fv.y - fw.y);
                        fa[4*i+2] = fabsf(fv.z - fw.z); fa[4*i+3] = fabsf(fv.w - fw.w);
                    }
                } else {
                    const float4* pa = (const float4*)(Ain + (size_t)gr * K + kb);
#pragma unroll
                    for (int i = 0; i < 8; i++) {
                        float4 f = pa[i];
                        fa[4*i+0] = f.x; fa[4*i+1] = f.y; fa[4*i+2] = f.z; fa[4*i+3] = f.w;
                    }
                }
            } else {
#pragma unroll
                for (int i = 0; i < 32; i++) fa[i] = 0.f;
            }
        }

        for (int c = 0; c < NC; c++) {
            int kb = c * 64 + phalf * 32;
            // convert fa -> hi/lo bf16x2 (apply affine+act for MODE 1)
            uint32_t hp[16], lp[16];
#pragma unroll
            for (int i = 0; i < 16; i++) {
                float f0 = fa[2*i], f1 = fa[2*i+1];
                if (MODE == 1) {
                    f0 = fmaf(f0, sS[kb + 2*i],     tS[kb + 2*i]);
                    f1 = fmaf(f1, sS[kb + 2*i + 1], tS[kb + 2*i + 1]);
                    f0 = f0 >= 0.f ? f0 : LSLOPE * f0;
                    f1 = f1 >= 0.f ? f1 : LSLOPE * f1;
                }
                uint32_t h;
                asm("cvt.rn.bf16x2.f32 %0, %1, %2;" : "=r"(h) : "f"(f1), "f"(f0));
                __nv_bfloat162 hh = *reinterpret_cast<__nv_bfloat162*>(&h);
                float r0 = f0 - __bfloat162float(hh.x);
                float r1 = f1 - __bfloat162float(hh.y);
                uint32_t l;
                asm("cvt.rn.bf16x2.f32 %0, %1, %2;" : "=r"(l) : "f"(r1), "f"(r0));
                hp[i] = h; lp[i] = l;
            }

            __syncthreads();   // previous mma phase done with A buffer (and B ready on c==0)

            uint32_t aH = sb + OFFA, aL = sb + OFFA + 16384;
#pragma unroll
            for (int u = 0; u < 4; u++) {
                uint32_t o = prow * 128 + phalf * 64 + u * 16; o ^= (o >> 3) & 0x70;
                STS128(hp[4*u], hp[4*u+1], hp[4*u+2], hp[4*u+3], aH + o);
                STS128(lp[4*u], lp[4*u+1], lp[4*u+2], lp[4*u+3], aL + o);
            }
            __syncthreads();   // A chunk visible

            // prefetch next chunk's globals into registers (hidden under mma)
            if (c + 1 < NC) {
                int kb2 = (c + 1) * 64 + phalf * 32;
                if (ok) {
                    if (MODE == 0) {
                        const float4* pv = (const float4*)(x + ((size_t)(bb * VN + vv)) * 256 + kb2);
                        const float4* pw = (const float4*)(x + ((size_t)(bb * VN + ww)) * 256 + kb2);
#pragma unroll
                        for (int i = 0; i < 8; i++) {
                            float4 fv = pv[i], fw = pw[i];
                            fa[4*i+0] = fabsf(fv.x - fw.x); fa[4*i+1] = fabsf(fv.y - fw.y);
                            fa[4*i+2] = fabsf(fv.z - fw.z); fa[4*i+3] = fabsf(fv.w - fw.w);
                        }
                    } else {
                        const float4* pa = (const float4*)(Ain + (size_t)gr * K + kb2);
#pragma unroll
                        for (int i = 0; i < 8; i++) {
                            float4 f = pa[i];
                            fa[4*i+0] = f.x; fa[4*i+1] = f.y; fa[4*i+2] = f.z; fa[4*i+3] = f.w;
                        }
                    }
                }
            }

            // ---- mma over chunk c ----
            uint32_t bHb = sb + OFFB + c * 16384;
            uint32_t bLb = sb + OFFB + NC * 16384 + c * 16384;
#pragma unroll
            for (int ksi = 0; ksi < 4; ksi++) {
                uint32_t Ah[4][4], Al[4][4], Bh[2][4], Bl[2][4];
#pragma unroll
                for (int i = 0; i < 4; i++) {
                    uint32_t o = (uint32_t)(wm * 64 + i * 16 + (lane & 15)) * 128
                               + ksi * 32 + ((lane >> 4) << 4);
                    o ^= (o >> 3) & 0x70;
                    LDSM4(Ah[i], aH + o);
                    LDSM4(Al[i], aL + o);
                }
#pragma unroll
                for (int j16 = 0; j16 < 2; j16++) {
                    uint32_t o = (uint32_t)(wn * 32 + j16 * 16 + (lane & 7) + ((lane >> 4) << 3)) * 128
                               + ksi * 32 + (((lane >> 3) & 1) << 4);
                    o ^= (o >> 3) & 0x70;
                    LDSM4(Bh[j16], bHb + o);
                    LDSM4(Bl[j16], bLb + o);
                }
#pragma unroll
                for (int i = 0; i < 4; i++) {
#pragma unroll
                    for (int j = 0; j < 4; j++) {
                        uint32_t h0 = Bh[j >> 1][(j & 1) * 2], h1 = Bh[j >> 1][(j & 1) * 2 + 1];
                        uint32_t l0 = Bl[j >> 1][(j & 1) * 2], l1 = Bl[j >> 1][(j & 1) * 2 + 1];
                        MMA16816(facc[i][j], Ah[i], h0, h1);
                        MMA16816(facc[i][j], Ah[i], l0, l1);
                        MMA16816(facc[i][j], Al[i], h0, h1);
                    }
                }
            }
        }

        // ---------- epilogue ----------
        float ps[8], pq[8];
#pragma unroll
        for (int q = 0; q < 8; q++) { ps[q] = 0.f; pq[q] = 0.f; }
        int mBase = mt * 128 + wm * 64;
#pragma unroll
        for (int i = 0; i < 4; i++) {
            int r0 = mBase + i * 16 + (lane >> 2);
            int r1 = r0 + 8;
            bool ok0 = r0 < MROWS, ok1 = r1 < MROWS;
            float wt0 = ok0 ? g_wpair[r0 % PAIRS] : 0.f;
            float wt1 = ok1 ? g_wpair[r1 % PAIRS] : 0.f;
#pragma unroll
            for (int j = 0; j < 4; j++) {
                int cc = wn * 32 + j * 8 + 2 * (lane & 3);
                float y0 = facc[i][j][0] + biasS[cc];
                float y1 = facc[i][j][1] + biasS[cc + 1];
                float y2 = facc[i][j][2] + biasS[cc];
                float y3 = facc[i][j][3] + biasS[cc + 1];
                if (ok0) *(float2*)&Cout[(size_t)r0 * ldc + colStart + cc] = make_float2(y0, y1);
                if (ok1) *(float2*)&Cout[(size_t)r1 * ldc + colStart + cc] = make_float2(y2, y3);
                ps[2*j]   += wt0 * y0 + wt1 * y2;
                ps[2*j+1] += wt0 * y1 + wt1 * y3;
                pq[2*j]   += wt0 * y0 * y0 + wt1 * y2 * y2;
                pq[2*j+1] += wt0 * y1 * y1 + wt1 * y3 * y3;
            }
        }
#pragma unroll
        for (int off = 4; off < 32; off <<= 1) {
#pragma unroll
            for (int q = 0; q < 8; q++) {
                ps[q] += __shfl_xor_sync(0xffffffffu, ps[q], off);
                pq[q] += __shfl_xor_sync(0xffffffffu, pq[q], off);
            }
        }
        if (lane < 4) {
#pragma unroll
            for (int j = 0; j < 4; j++) {
                wSsum[w * 32 + j * 8 + 2 * lane]     = ps[2*j];
                wSsum[w * 32 + j * 8 + 2 * lane + 1] = ps[2*j+1];
                wSsq [w * 32 + j * 8 + 2 * lane]     = pq[2*j];
                wSsq [w * 32 + j * 8 + 2 * lane + 1] = pq[2*j+1];
            }
        }
        __syncthreads();
        if (tid < 128) {
            int base0 = ((tid >> 5) * 2) * 32 + (tid & 31);
            sumAcc[tid] += wSsum[base0] + wSsum[base0 + 32];
            sqAcc [tid] += wSsq [base0] + wSsq [base0 + 32];
        }
        __syncthreads();
    }

    if (tid < 128) {
        g_psum[(size_t)(colStart + tid) * PSTRIDE + blockIdx.x] = sumAcc[tid];
        g_psq [(size_t)(colStart + tid) * PSTRIDE + blockIdx.x] = sqAcc[tid];
    }
}

// ---------------- reduce 148 partials -> BN affine ----------------
__global__ void stats2(int outOff, const float* __restrict__ gamma, const float* __restrict__ beta) {
    int c = blockIdx.x, t = threadIdx.x;
    double s = 0.0, q = 0.0;
    for (int i = t; i < NCTA; i += 32) {
        s += (double)g_psum[(size_t)c * PSTRIDE + i];
        q += (double)g_psq [(size_t)c * PSTRIDE + i];
    }
#pragma unroll
    for (int o = 16; o > 0; o >>= 1) {
        s += __shfl_down_sync(0xffffffffu, s, o);
        q += __shfl_down_sync(0xffffffffu, q, o);
    }
    if (t == 0) {
        double mean = s / CNT;
        double var  = q / CNT - mean * mean;
        float inv = rsqrtf((float)var + 1e-5f);
        float sc  = gamma[c] * inv;
        g_sArr[outOff + c] = sc;
        g_tArr[outOff + c] = beta[c] - (float)mean * sc;
    }
}

// ---------------- final linear -> symmetric logit scatter ----------------
__global__ void logits_kernel(const float* __restrict__ w4, const float* __restrict__ b4) {
    int warp = threadIdx.x >> 5, lane = threadIdx.x & 31;
    int r = blockIdx.x * 8 + warp;
    if (r >= MROWS) return;
    int c = lane * 4;
    float4 v  = *(const float4*)&g_bufA[(size_t)r * 128 + c];
    float4 s4 = *(const float4*)&g_sArr[768 + c];
    float4 t4 = *(const float4*)&g_tArr[768 + c];
    float4 w  = *(const float4*)&w4[c];
    float a, sum = 0.f;
    a = v.x * s4.x + t4.x; a = a >= 0.f ? a : LSLOPE * a; sum += a * w.x;
    a = v.y * s4.y + t4.y; a = a >= 0.f ? a : LSLOPE * a; sum += a * w.y;
    a = v.z * s4.z + t4.z; a = a >= 0.f ? a : LSLOPE * a; sum += a * w.z;
    a = v.w * s4.w + t4.w; a = a >= 0.f ? a : LSLOPE * a; sum += a * w.w;
#pragma unroll
    for (int off = 16; off > 0; off >>= 1) sum += __shfl_down_sync(0xffffffffu, sum, off);
    if (lane == 0) {
        float lg = sum + b4[0];
        int b = r / PAIRS, p = r - b * PAIRS;
        int2 vw = g_vw[p];
        g_logits[((size_t)b * VN + vw.x) * VN + vw.y] = lg;
        g_logits[((size_t)b * VN + vw.y) * VN + vw.x] = lg;
    }
}

// ---------------- row softmax + top-K mask ----------------
__global__ void softmax_topk(float* __restrict__ out) {
    int bv = blockIdx.x;
    int b = bv / VN, v = bv % VN;
    int t = threadIdx.x;
    __shared__ float sl[204];
    __shared__ float red[256];

    float lv = -3.402823466e38f;
    if (t < VN) { lv = g_logits[((size_t)b * VN + v) * VN + t]; sl[t] = lv; }
    red[t] = lv;
    __syncthreads();
    for (int s = 128; s > 0; s >>= 1) {
        if (t < s) red[t] = fmaxf(red[t], red[t + s]);
        __syncthreads();
    }
    float mx = red[0];
    __syncthreads();
    float e = (t < VN) ? __expf(lv - mx) : 0.f;
    red[t] = e;
    __syncthreads();
    for (int s = 128; s > 0; s >>= 1) {
        if (t < s) red[t] += red[t + s];
        __syncthreads();
    }
    float inv = 1.f / red[0];
    if (t < VN) {
        int cnt = 0;
        for (int j = 0; j < VN; j++) {
            float lj = sl[j];
            cnt += (lj > lv) || (lj == lv && j < t);
        }
        out[((size_t)b * VN + v) * VN + t] = (cnt < KSEL) ? e * inv : 0.f;
    }
}

// ---------------- launch ----------------
extern "C" void kernel_launch(void* const* d_in, const int* in_sizes, int n_in,
                              void* d_out, int out_size)
{
    (void)in_sizes; (void)n_in; (void)out_size;
    const float* x   = (const float*)d_in[0];
    const float* w0  = (const float*)d_in[1];
    const float* b0  = (const float*)d_in[2];
    const float* g0  = (const float*)d_in[3];
    const float* be0 = (const float*)d_in[4];
    const float* w1  = (const float*)d_in[5];
    const float* b1  = (const float*)d_in[6];
    const float* g1  = (const float*)d_in[7];
    const float* be1 = (const float*)d_in[8];
    const float* w2  = (const float*)d_in[9];
    const float* b2  = (const float*)d_in[10];
    const float* g2  = (const float*)d_in[11];
    const float* be2 = (const float*)d_in[12];
    const float* w3  = (const float*)d_in[13];
    const float* b3  = (const float*)d_in[14];
    const float* g3  = (const float*)d_in[15];
    const float* be3 = (const float*)d_in[16];
    const float* w4  = (const float*)d_in[17];
    const float* b4  = (const float*)d_in[18];

    // smem: 8192 header + 32768 A + NC*16384*2 B
    const int SM256 = 8192 + 32768 + 8 * 16384;   // 172032
    const int SM128 = 8192 + 32768 + 4 * 16384;   // 106496
    cudaFuncSetAttribute(gemm_mma<256, 0, 0>, cudaFuncAttributeMaxDynamicSharedMemorySize, SM256);
    cudaFuncSetAttribute(gemm_mma<256, 1, 1>, cudaFuncAttributeMaxDynamicSharedMemorySize, SM256);
    cudaFuncSetAttribute(gemm_mma<256, 1, 0>, cudaFuncAttributeMaxDynamicSharedMemorySize, SM256);
    cudaFuncSetAttribute(gemm_mma<128, 1, 1>, cudaFuncAttributeMaxDynamicSharedMemorySize, SM128);

    init_lut<<<1, 256>>>();
    wsplit<<<64, 256>>>(w0, w1, w2, w3);

    // L0: absdiff(x) @ w0^T -> bufB   (K=256, N=256)
    gemm_mma<256, 0, 0><<<dim3(NCTA, 2), 256, SM256>>>(256, 0, x, b0, 0);
    stats2<<<256, 32>>>(0, g0, be0);

    // L1: act(bn0(bufB)) @ w1^T -> bufA   (K=256, N=256)
    gemm_mma<256, 1, 1><<<dim3(NCTA, 2), 256, SM256>>>(256, 65536, x, b1, 0);
    stats2<<<256, 32>>>(256, g1, be1);

    // L2: act(bn1(bufA)) @ w2^T -> bufB   (K=256, N=128)
    gemm_mma<256, 1, 0><<<dim3(NCTA, 1), 256, SM256>>>(128, 131072, x, b2, 256);
    stats2<<<128, 32>>>(512, g2, be2);

    // L3: act(bn2(bufB)) @ w3^T -> bufA   (K=128, N=128)
    gemm_mma<128, 1, 1><<<dim3(NCTA, 1), 256, SM128>>>(128, 163840, x, b3, 512);
    stats2<<<128, 32>>>(768, g3, be3);

    // L4 + symmetric scatter, then softmax/top-K
    logits_kernel<<<MROWS / 8, 256>>>(w4, b4);
    softmax_topk<<<BATCH * VN, 256>>>((float*)d_out);
}